// round 2
// baseline (speedup 1.0000x reference)
#include <cuda_runtime.h>
#include <stdint.h>

#define NBATCH 16
#define SEQL   100
#define DIM    512
#define HW     16384
#define NHEAD  8
#define HD     64
#define MROWS  (NBATCH*SEQL)
#define LOG2E  1.4426950408889634f

// ---------------- scratch (device globals: no allocation allowed) ----------
__device__ float g_K[(size_t)NBATCH*HW*DIM];   // 512 MB
__device__ float g_V[(size_t)NBATCH*HW*DIM];   // 512 MB
__device__ float g_Q[MROWS*DIM];               // scaled q
__device__ float g_AO[MROWS*DIM];              // attention output
__device__ float g_T[MROWS*DIM];               // gemm temp
__device__ float g_X[MROWS*DIM];               // after ln0
__device__ float g_H[MROWS*DIM];               // ffn hidden

// ---------------- helpers ---------------------------------------------------
__device__ __forceinline__ uint32_t f2tf(float x) {
    uint32_t u; asm("cvt.rna.tf32.f32 %0, %1;" : "=r"(u) : "f"(x)); return u;
}
__device__ __forceinline__ void mma8(float* c, const uint32_t* a, const uint32_t* b) {
    asm volatile("mma.sync.aligned.m16n8k8.row.col.f32.tf32.tf32.f32 "
                 "{%0,%1,%2,%3}, {%4,%5,%6,%7}, {%8,%9}, {%0,%1,%2,%3};"
                 : "+f"(c[0]), "+f"(c[1]), "+f"(c[2]), "+f"(c[3])
                 : "r"(a[0]), "r"(a[1]), "r"(a[2]), "r"(a[3]),
                   "r"(b[0]), "r"(b[1]));
}
__device__ __forceinline__ float ex2f(float x) {
    float y; asm("ex2.approx.f32 %0, %1;" : "=f"(y) : "f"(x)); return y;
}
__device__ __forceinline__ void cp16(uint32_t dst, const void* src, int nbytes) {
    asm volatile("cp.async.ca.shared.global [%0], [%1], 16, %2;"
                 :: "r"(dst), "l"(src), "r"(nbytes));
}

// ---------------- generic GEMM: C[M,N] = relu?(alpha*A[M,512]@B[N,512]^T + bias)
#define SA 44   // smem row stride (floats): 44%32==12, 44*4 bytes 16B-aligned

__global__ __launch_bounds__(256, 2)
void gemm_tn(const float* __restrict__ A, const float* __restrict__ B,
             float* __restrict__ C, int M, int N,
             long long sAb, long long sBb, long long sCb,
             float alpha, const float* __restrict__ bias, int relu)
{
    A += (long long)blockIdx.z * sAb;
    B += (long long)blockIdx.z * sBb;
    C += (long long)blockIdx.z * sCb;
    const int bm = blockIdx.y * 128, bn = blockIdx.x * 128;
    const int tid = threadIdx.x, lane = tid & 31, warp = tid >> 5;
    const int wm = warp >> 1, wn = warp & 1;          // 4x2 warp grid
    const int g = lane >> 2, t = lane & 3;

    extern __shared__ float sm[];
    float* As = sm;                  // [2][128][SA]
    float* Bs = sm + 2 * 128 * SA;   // [2][128][SA]

    const int lrow = tid >> 1;
    const int lcb  = (tid & 1) * 16;                  // float col base (0/16)
    const int arow = bm + lrow;
    const int abytes = (arow < M) ? 16 : 0;
    const float* agp = A + (long long)arow * DIM + lcb;
    const float* bgp = B + (long long)(bn + lrow) * DIM + lcb;
    uint32_t sbase = (uint32_t)__cvta_generic_to_shared(sm);
    uint32_t sa0 = sbase + (uint32_t)(lrow * SA + lcb) * 4u;
    uint32_t sb0 = sbase + (uint32_t)(2*128*SA + lrow * SA + lcb) * 4u;
    const uint32_t bufbytes = 128 * SA * 4;

    float acc[2][8][4];
    #pragma unroll
    for (int i = 0; i < 2; ++i)
        #pragma unroll
        for (int j = 0; j < 8; ++j)
            #pragma unroll
            for (int k = 0; k < 4; ++k) acc[i][j][k] = 0.f;

    // prologue: stage 0 into buffer 0
    #pragma unroll
    for (int i = 0; i < 4; ++i) {
        cp16(sa0 + i*16, agp + i*4, abytes);
        cp16(sb0 + i*16, bgp + i*4, 16);
    }
    asm volatile("cp.async.commit_group;");

    #pragma unroll 1
    for (int kt = 0; kt < 16; ++kt) {
        if (kt < 15) {
            int buf = (kt + 1) & 1;
            const float* ag = agp + (kt + 1) * 32;
            const float* bg = bgp + (kt + 1) * 32;
            #pragma unroll
            for (int i = 0; i < 4; ++i) {
                cp16(sa0 + buf*bufbytes + i*16, ag + i*4, abytes);
                cp16(sb0 + buf*bufbytes + i*16, bg + i*4, 16);
            }
            asm volatile("cp.async.commit_group;");
            asm volatile("cp.async.wait_group 1;");
        } else {
            asm volatile("cp.async.wait_group 0;");
        }
        __syncthreads();
        const float* Ab = As + (kt & 1) * 128 * SA;
        const float* Bb = Bs + (kt & 1) * 128 * SA;
        #pragma unroll
        for (int ks = 0; ks < 4; ++ks) {
            uint32_t af[2][4];
            #pragma unroll
            for (int fm = 0; fm < 2; ++fm) {
                int r = wm*32 + fm*16;
                af[fm][0] = f2tf(Ab[(r+g)  *SA + ks*8 + t]);
                af[fm][1] = f2tf(Ab[(r+g+8)*SA + ks*8 + t]);
                af[fm][2] = f2tf(Ab[(r+g)  *SA + ks*8 + t + 4]);
                af[fm][3] = f2tf(Ab[(r+g+8)*SA + ks*8 + t + 4]);
            }
            uint32_t bf[8][2];
            #pragma unroll
            for (int fn = 0; fn < 8; ++fn) {
                int cb = wn*64 + fn*8 + g;
                bf[fn][0] = f2tf(Bb[cb*SA + ks*8 + t]);
                bf[fn][1] = f2tf(Bb[cb*SA + ks*8 + t + 4]);
            }
            #pragma unroll
            for (int fm = 0; fm < 2; ++fm)
                #pragma unroll
                for (int fn = 0; fn < 8; ++fn)
                    mma8(acc[fm][fn], af[fm], bf[fn]);
        }
        __syncthreads();
    }

    // epilogue
    #pragma unroll
    for (int fm = 0; fm < 2; ++fm) {
        int r0 = bm + wm*32 + fm*16 + g;
        int r1 = r0 + 8;
        #pragma unroll
        for (int fn = 0; fn < 8; ++fn) {
            int c = bn + wn*64 + fn*8 + 2*t;
            float b0v = 0.f, b1v = 0.f;
            if (bias) { b0v = bias[c]; b1v = bias[c+1]; }
            float v0 = acc[fm][fn][0]*alpha + b0v;
            float v1 = acc[fm][fn][1]*alpha + b1v;
            float v2 = acc[fm][fn][2]*alpha + b0v;
            float v3 = acc[fm][fn][3]*alpha + b1v;
            if (relu) {
                v0 = fmaxf(v0, 0.f); v1 = fmaxf(v1, 0.f);
                v2 = fmaxf(v2, 0.f); v3 = fmaxf(v3, 0.f);
            }
            if (r0 < M) *(float2*)&C[(long long)r0 * N + c] = make_float2(v0, v1);
            if (r1 < M) *(float2*)&C[(long long)r1 * N + c] = make_float2(v2, v3);
        }
    }
}

// ---------------- attention: one CTA per (b,h), flash-style ----------------
#define QKS 68    // Q/K smem stride (68%32==4)
#define VST 72    // V smem stride (72%32==8)
#define PST 132   // P smem stride (132%32==4)

__global__ __launch_bounds__(256, 1)
void attn_k()
{
    extern __shared__ float sm[];
    float* Qs    = sm;                    // 128*68
    float* Ks    = Qs + 128*QKS;          // 128*68
    float* Vs    = Ks + 128*QKS;          // 128*72
    float* Ps    = Vs + 128*VST;          // 128*132
    float* denom = Ps + 128*PST;          // 128
    float* rsum  = denom + 128;           // 128

    const int b = blockIdx.x >> 3, h = blockIdx.x & 7;
    const int tid = threadIdx.x, lane = tid & 31, warp = tid >> 5;
    const int g = lane >> 2, t = lane & 3;
    const int wm = warp >> 1, wn = warp & 1;

    // load Q tile [128(100) x 64], zero-pad dead rows
    {
        int r = tid >> 1;
        int cb = (tid & 1) * 32;
        const float* src = g_Q + (long long)(b*SEQL + (r < SEQL ? r : 0))*DIM + h*HD + cb;
        #pragma unroll
        for (int j = 0; j < 8; ++j) {
            float4 v = make_float4(0.f, 0.f, 0.f, 0.f);
            if (r < SEQL) v = *(const float4*)(src + j*4);
            *(float4*)&Qs[r*QKS + cb + j*4] = v;
        }
    }
    if (tid < 128) denom[tid] = 0.f;

    float oacc[2][4][4];
    #pragma unroll
    for (int i = 0; i < 2; ++i)
        #pragma unroll
        for (int j = 0; j < 4; ++j)
            #pragma unroll
            for (int k = 0; k < 4; ++k) oacc[i][j][k] = 0.f;

    for (int m0 = 0; m0 < HW; m0 += 128) {
        __syncthreads();   // prev PV done with Ks/Vs/Ps; prev denom+= done
        {
            int r = tid >> 1;
            int cb = (tid & 1) * 32;
            const float* kp = g_K + (long long)(b*HW + m0 + r)*DIM + h*HD + cb;
            const float* vp = g_V + (long long)(b*HW + m0 + r)*DIM + h*HD + cb;
            #pragma unroll
            for (int j = 0; j < 8; ++j)
                *(float4*)&Ks[r*QKS + cb + j*4] = *(const float4*)(kp + j*4);
            #pragma unroll
            for (int j = 0; j < 8; ++j)
                *(float4*)&Vs[r*VST + cb + j*4] = *(const float4*)(vp + j*4);
        }
        if (tid < 128) rsum[tid] = 0.f;
        __syncthreads();

        // S = Q @ K^T  (warp tile: 32 rows x 64 keys)
        float sacc[2][8][4];
        #pragma unroll
        for (int i = 0; i < 2; ++i)
            #pragma unroll
            for (int j = 0; j < 8; ++j)
                #pragma unroll
                for (int k = 0; k < 4; ++k) sacc[i][j][k] = 0.f;
        #pragma unroll
        for (int ks = 0; ks < 8; ++ks) {
            uint32_t af[2][4];
            #pragma unroll
            for (int fm = 0; fm < 2; ++fm) {
                int r = wm*32 + fm*16;
                af[fm][0] = f2tf(Qs[(r+g)  *QKS + ks*8 + t]);
                af[fm][1] = f2tf(Qs[(r+g+8)*QKS + ks*8 + t]);
                af[fm][2] = f2tf(Qs[(r+g)  *QKS + ks*8 + t + 4]);
                af[fm][3] = f2tf(Qs[(r+g+8)*QKS + ks*8 + t + 4]);
            }
            uint32_t bf[8][2];
            #pragma unroll
            for (int fn = 0; fn < 8; ++fn) {
                int key = wn*64 + fn*8 + g;
                bf[fn][0] = f2tf(Ks[key*QKS + ks*8 + t]);
                bf[fn][1] = f2tf(Ks[key*QKS + ks*8 + t + 4]);
            }
            #pragma unroll
            for (int fm = 0; fm < 2; ++fm)
                #pragma unroll
                for (int fn = 0; fn < 8; ++fn)
                    mma8(sacc[fm][fn], af[fm], bf[fn]);
        }

        // p = exp(s) ; row sums ; store P to smem
        #pragma unroll
        for (int fm = 0; fm < 2; ++fm) {
            float rs0 = 0.f, rs1 = 0.f;
            int row0 = wm*32 + fm*16 + g;
            #pragma unroll
            for (int fn = 0; fn < 8; ++fn) {
                float p0 = ex2f(sacc[fm][fn][0] * LOG2E);
                float p1 = ex2f(sacc[fm][fn][1] * LOG2E);
                float p2 = ex2f(sacc[fm][fn][2] * LOG2E);
                float p3 = ex2f(sacc[fm][fn][3] * LOG2E);
                rs0 += p0 + p1; rs1 += p2 + p3;
                int c = wn*64 + fn*8 + 2*t;
                *(float2*)&Ps[row0*PST + c]     = make_float2(p0, p1);
                *(float2*)&Ps[(row0+8)*PST + c] = make_float2(p2, p3);
            }
            rs0 += __shfl_xor_sync(0xffffffffu, rs0, 1);
            rs0 += __shfl_xor_sync(0xffffffffu, rs0, 2);
            rs1 += __shfl_xor_sync(0xffffffffu, rs1, 1);
            rs1 += __shfl_xor_sync(0xffffffffu, rs1, 2);
            if (t == 0) {
                atomicAdd(&rsum[row0], rs0);
                atomicAdd(&rsum[row0 + 8], rs1);
            }
        }
        __syncthreads();   // P + rsum complete
        if (tid < 128) denom[tid] += rsum[tid];

        // O += P @ V  (warp tile: 32 rows x 32 d, K=128 keys)
        #pragma unroll
        for (int kk = 0; kk < 16; ++kk) {
            uint32_t af[2][4];
            #pragma unroll
            for (int fm = 0; fm < 2; ++fm) {
                int r = wm*32 + fm*16;
                af[fm][0] = f2tf(Ps[(r+g)  *PST + kk*8 + t]);
                af[fm][1] = f2tf(Ps[(r+g+8)*PST + kk*8 + t]);
                af[fm][2] = f2tf(Ps[(r+g)  *PST + kk*8 + t + 4]);
                af[fm][3] = f2tf(Ps[(r+g+8)*PST + kk*8 + t + 4]);
            }
            uint32_t bf[4][2];
            #pragma unroll
            for (int fn = 0; fn < 4; ++fn) {
                int d = wn*32 + fn*8 + g;
                bf[fn][0] = f2tf(Vs[(kk*8 + t)    *VST + d]);
                bf[fn][1] = f2tf(Vs[(kk*8 + t + 4)*VST + d]);
            }
            #pragma unroll
            for (int fm = 0; fm < 2; ++fm)
                #pragma unroll
                for (int fn = 0; fn < 4; ++fn)
                    mma8(oacc[fm][fn], af[fm], bf[fn]);
        }
    }
    __syncthreads();

    #pragma unroll
    for (int fm = 0; fm < 2; ++fm) {
        int row0 = wm*32 + fm*16 + g;
        int row1 = row0 + 8;
        float i0 = (row0 < SEQL) ? 1.f / denom[row0] : 0.f;
        float i1 = (row1 < SEQL) ? 1.f / denom[row1] : 0.f;
        #pragma unroll
        for (int fn = 0; fn < 4; ++fn) {
            int c = h*HD + wn*32 + fn*8 + 2*t;
            if (row0 < SEQL)
                *(float2*)&g_AO[(long long)(b*SEQL + row0)*DIM + c] =
                    make_float2(oacc[fm][fn][0]*i0, oacc[fm][fn][1]*i0);
            if (row1 < SEQL)
                *(float2*)&g_AO[(long long)(b*SEQL + row1)*DIM + c] =
                    make_float2(oacc[fm][fn][2]*i1, oacc[fm][fn][3]*i1);
        }
    }
}

// ---------------- LayerNorm(a + t) ------------------------------------------
__global__ void ln_add_k(const float* __restrict__ a, const float* __restrict__ tt,
                         const float* __restrict__ w, const float* __restrict__ bb,
                         float* __restrict__ o)
{
    __shared__ float red[4];
    __shared__ float smu, sinv;
    int row = blockIdx.x, tid = threadIdx.x;   // 128 threads
    const float* pa = a  + (long long)row * DIM;
    const float* pt = tt + (long long)row * DIM;
    float v[4]; float s = 0.f;
    #pragma unroll
    for (int i = 0; i < 4; ++i) {
        v[i] = pa[tid + i*128] + pt[tid + i*128];
        s += v[i];
    }
    #pragma unroll
    for (int off = 16; off; off >>= 1) s += __shfl_xor_sync(0xffffffffu, s, off);
    if ((tid & 31) == 0) red[tid >> 5] = s;
    __syncthreads();
    if (tid == 0) smu = (red[0] + red[1] + red[2] + red[3]) * (1.f / 512.f);
    __syncthreads();
    float mu = smu; float s2 = 0.f;
    #pragma unroll
    for (int i = 0; i < 4; ++i) { float d = v[i] - mu; s2 += d * d; }
    #pragma unroll
    for (int off = 16; off; off >>= 1) s2 += __shfl_xor_sync(0xffffffffu, s2, off);
    if ((tid & 31) == 0) red[tid >> 5] = s2;
    __syncthreads();
    if (tid == 0) sinv = rsqrtf((red[0] + red[1] + red[2] + red[3]) * (1.f / 512.f) + 1e-5f);
    __syncthreads();
    float inv = sinv;
    #pragma unroll
    for (int i = 0; i < 4; ++i) {
        int c = tid + i*128;
        o[(long long)row * DIM + c] = (v[i] - mu) * inv * w[c] + bb[c];
    }
}

// ---------------- launch -----------------------------------------------------
extern "C" void kernel_launch(void* const* d_in, const int* in_sizes, int n_in,
                              void* d_out, int out_size)
{
    const float* query = (const float*)d_in[0];
    const float* feats = (const float*)d_in[1];
    const float* Wq    = (const float*)d_in[2];
    const float* Wk    = (const float*)d_in[3];
    const float* Wv    = (const float*)d_in[4];
    const float* Wp    = (const float*)d_in[5];
    const float* bp    = (const float*)d_in[6];
    const float* W1    = (const float*)d_in[7];
    const float* b1    = (const float*)d_in[8];
    const float* W2    = (const float*)d_in[9];
    const float* b2    = (const float*)d_in[10];
    const float* ln0w  = (const float*)d_in[11];
    const float* ln0b  = (const float*)d_in[12];
    const float* ln2w  = (const float*)d_in[13];
    const float* ln2b  = (const float*)d_in[14];
    float* out = (float*)d_out;

    float *pK, *pV, *pQ, *pAO, *pT, *pX, *pH;
    cudaGetSymbolAddress((void**)&pK,  g_K);
    cudaGetSymbolAddress((void**)&pV,  g_V);
    cudaGetSymbolAddress((void**)&pQ,  g_Q);
    cudaGetSymbolAddress((void**)&pAO, g_AO);
    cudaGetSymbolAddress((void**)&pT,  g_T);
    cudaGetSymbolAddress((void**)&pX,  g_X);
    cudaGetSymbolAddress((void**)&pH,  g_H);

    const int GS = 2 * 2 * 128 * SA * 4;                       // 90112
    const int AS = (128*QKS*2 + 128*VST + 128*PST + 256) * 4;  // 175104
    cudaFuncSetAttribute(gemm_tn, cudaFuncAttributeMaxDynamicSharedMemorySize, GS);
    cudaFuncSetAttribute(attn_k,  cudaFuncAttributeMaxDynamicSharedMemorySize, AS);

    // 1. q = 0.125 * query @ Wq^T
    gemm_tn<<<dim3(4, 13, 1), 256, GS>>>(query, Wq, pQ, MROWS, DIM,
                                         0, 0, 0, 0.125f, nullptr, 0);
    // 2-3. K,V projections
    gemm_tn<<<dim3(4, 2048, 1), 256, GS>>>(feats, Wk, pK, NBATCH*HW, DIM,
                                           0, 0, 0, 1.f, nullptr, 0);
    gemm_tn<<<dim3(4, 2048, 1), 256, GS>>>(feats, Wv, pV, NBATCH*HW, DIM,
                                           0, 0, 0, 1.f, nullptr, 0);
    // 4. attention -> g_AO
    attn_k<<<NBATCH * NHEAD, 256, AS>>>();
    // 5. mask = q @ K^T per batch, straight into d_out tail
    gemm_tn<<<dim3(HW/128, 1, NBATCH), 256, GS>>>(pQ, pK, out + MROWS*DIM,
                                                  SEQL, HW,
                                                  (long long)SEQL*DIM,
                                                  (long long)HW*DIM,
                                                  (long long)SEQL*HW,
                                                  1.f, nullptr, 0);
    // 6. attn_out @ Wp^T + bp
    gemm_tn<<<dim3(4, 13, 1), 256, GS>>>(pAO, Wp, pT, MROWS, DIM,
                                         0, 0, 0, 1.f, bp, 0);
    // 7. x = LN(query + t)
    ln_add_k<<<MROWS, 128>>>(query, pT, ln0w, ln0b, pX);
    // 8. h = relu(x @ W1^T + b1)
    gemm_tn<<<dim3(4, 13, 1), 256, GS>>>(pX, W1, pH, MROWS, DIM,
                                         0, 0, 0, 1.f, b1, 1);
    // 9. f = h @ W2^T + b2
    gemm_tn<<<dim3(4, 13, 1), 256, GS>>>(pH, W2, pT, MROWS, DIM,
                                         0, 0, 0, 1.f, b2, 0);
    // 10. y = LN(x + f) -> d_out head
    ln_add_k<<<MROWS, 128>>>(pX, pT, ln2w, ln2b, out);
}

// round 5
// speedup vs baseline: 1.6399x; 1.6399x over previous
#include <cuda_runtime.h>
#include <cuda_fp16.h>
#include <stdint.h>

#define NBATCH 16
#define SEQL   100
#define DIM    512
#define HW     16384
#define NHEAD  8
#define HD     64
#define MROWS  (NBATCH*SEQL)
#define LOG2E  1.4426950408889634f
#define NSPLIT 8
#define SPLEN  (HW / NSPLIT)

// ---------------- scratch (device globals; no allocation allowed) -------------
__device__ __half g_K2[(size_t)NBATCH*HW*DIM];   // 256 MB
__device__ __half g_V2[(size_t)NBATCH*HW*DIM];   // 256 MB
__device__ float  g_Q [MROWS*DIM];
__device__ float  g_AO[MROWS*DIM];
__device__ float  g_T [MROWS*DIM];
__device__ float  g_X [MROWS*DIM];
__device__ float  g_H [MROWS*DIM];
__device__ float  g_PO[(size_t)NBATCH*NHEAD*NSPLIT*SEQL*HD];  // partial numerators
__device__ float  g_PD[NBATCH*NHEAD*NSPLIT*128];              // partial denominators

// ---------------- helpers ------------------------------------------------------
__device__ __forceinline__ uint32_t smem_u32(const void* p) {
    uint32_t a;
    asm("{ .reg .u64 t; cvta.to.shared.u64 t, %1; cvt.u32.u64 %0, t; }" : "=r"(a) : "l"(p));
    return a;
}
__device__ __forceinline__ void ldm4(uint32_t* r, uint32_t addr) {
    asm volatile("ldmatrix.sync.aligned.m8n8.x4.shared.b16 {%0,%1,%2,%3}, [%4];"
                 : "=r"(r[0]), "=r"(r[1]), "=r"(r[2]), "=r"(r[3]) : "r"(addr));
}
__device__ __forceinline__ void ldm4t(uint32_t* r, uint32_t addr) {
    asm volatile("ldmatrix.sync.aligned.m8n8.x4.trans.shared.b16 {%0,%1,%2,%3}, [%4];"
                 : "=r"(r[0]), "=r"(r[1]), "=r"(r[2]), "=r"(r[3]) : "r"(addr));
}
__device__ __forceinline__ void mmah(float* c, const uint32_t* a, uint32_t b0, uint32_t b1) {
    asm volatile("mma.sync.aligned.m16n8k16.row.col.f32.f16.f16.f32 "
                 "{%0,%1,%2,%3},{%4,%5,%6,%7},{%8,%9},{%0,%1,%2,%3};"
                 : "+f"(c[0]), "+f"(c[1]), "+f"(c[2]), "+f"(c[3])
                 : "r"(a[0]), "r"(a[1]), "r"(a[2]), "r"(a[3]), "r"(b0), "r"(b1));
}
__device__ __forceinline__ float ex2f(float x) {
    float y; asm("ex2.approx.f32 %0, %1;" : "=f"(y) : "f"(x)); return y;
}

// ---------------- fp16 GEMM: C[M,N-block] = relu?(alpha * A[M,512] @ B^T + bias)
// BM=128, BN=128, BK=16. A f32; B f32 or half; C f32 or half.
#define GSH 24   // smem halves stride: 48B rows -> conflict-free ldmatrix

__global__ __launch_bounds__(256, 2)
void gemm_h(const float* __restrict__ A,
            const void* __restrict__ B0v, const void* __restrict__ B1v,
            void* __restrict__ C0v, void* __restrict__ C1v,
            int M, int ldc, int nsplitBlk, int bhalf, int outhalf,
            float alpha, const float* __restrict__ bias, int relu,
            long long sAz, long long sBz, long long sCz)
{
    __shared__ __half sAB[2][2][128*GSH];   // [buf][mat] 24.6 KB
    const int tid = threadIdx.x, lane = tid & 31, warp = tid >> 5;
    const int wm = warp >> 1, wn = warp & 1;
    const int g = lane >> 2, t = lane & 3;
    const int bm = blockIdx.y * 128;
    const int bx = blockIdx.x;
    const long long z = blockIdx.z;

    const void* Bv; void* Cv; int bc;
    if (bx >= nsplitBlk) { Bv = B1v; Cv = C1v; bc = (bx - nsplitBlk) * 128; }
    else                 { Bv = B0v; Cv = C0v; bc = bx * 128; }

    const int rowA = tid >> 1, cA = (tid & 1) * 8;
    int arow = bm + rowA; if (arow > M - 1) arow = M - 1;
    const float*  Af = A + z * sAz + (long long)arow * 512 + cA;
    const long long boff = (long long)(bc + rowA) * 512 + cA + z * sBz;
    const float*  Bf = (const float*)Bv + boff;
    const __half* Bh = (const __half*)Bv + boff;

    float acc[2][8][4];
    #pragma unroll
    for (int i = 0; i < 2; ++i)
        #pragma unroll
        for (int j = 0; j < 8; ++j)
            #pragma unroll
            for (int k = 0; k < 4; ++k) acc[i][j][k] = 0.f;

    float4 ra0, ra1, rb0, rb1; uint4 rbh;
    const uint32_t base = smem_u32(sAB);

    // ---- staging helpers ----
    #define LDREG(kt) do {                                                   \
        ra0 = *(const float4*)(Af + (kt)*16);                                \
        ra1 = *(const float4*)(Af + (kt)*16 + 4);                            \
        if (bhalf) rbh = *(const uint4*)(Bh + (kt)*16);                      \
        else { rb0 = *(const float4*)(Bf + (kt)*16);                         \
               rb1 = *(const float4*)(Bf + (kt)*16 + 4); }                   \
    } while (0)
    #define STSH(buf) do {                                                   \
        __half2 ha[4];                                                       \
        ha[0] = __floats2half2_rn(ra0.x, ra0.y);                             \
        ha[1] = __floats2half2_rn(ra0.z, ra0.w);                             \
        ha[2] = __floats2half2_rn(ra1.x, ra1.y);                             \
        ha[3] = __floats2half2_rn(ra1.z, ra1.w);                             \
        *(uint4*)&sAB[buf][0][rowA*GSH + cA] = *(uint4*)ha;                  \
        if (bhalf) { *(uint4*)&sAB[buf][1][rowA*GSH + cA] = rbh; }           \
        else {                                                               \
            __half2 hb[4];                                                   \
            hb[0] = __floats2half2_rn(rb0.x, rb0.y);                         \
            hb[1] = __floats2half2_rn(rb0.z, rb0.w);                         \
            hb[2] = __floats2half2_rn(rb1.x, rb1.y);                         \
            hb[3] = __floats2half2_rn(rb1.z, rb1.w);                         \
            *(uint4*)&sAB[buf][1][rowA*GSH + cA] = *(uint4*)hb;              \
        }                                                                    \
    } while (0)

    LDREG(0); STSH(0); __syncthreads();

    #pragma unroll 1
    for (int kt = 0; kt < 32; ++kt) {
        if (kt < 31) LDREG(kt + 1);
        {
            const int buf = kt & 1;
            const uint32_t ab = base + (uint32_t)((buf*2 + 0) * 128 * GSH) * 2u;
            const uint32_t bb = base + (uint32_t)((buf*2 + 1) * 128 * GSH) * 2u;
            uint32_t afr[2][4];
            #pragma unroll
            for (int fm = 0; fm < 2; ++fm)
                ldm4(afr[fm], ab + (uint32_t)((wm*32 + fm*16 + (lane & 15))*GSH
                                              + (lane >> 4)*8) * 2u);
            #pragma unroll
            for (int nb = 0; nb < 4; ++nb) {
                uint32_t bfr[4];
                ldm4(bfr, bb + (uint32_t)((wn*64 + nb*16 + (lane >> 4)*8 + (lane & 7))*GSH
                                          + ((lane >> 3) & 1)*8) * 2u);
                #pragma unroll
                for (int fm = 0; fm < 2; ++fm) {
                    mmah(acc[fm][2*nb],     afr[fm], bfr[0], bfr[1]);
                    mmah(acc[fm][2*nb + 1], afr[fm], bfr[2], bfr[3]);
                }
            }
        }
        if (kt < 31) { STSH((kt + 1) & 1); __syncthreads(); }
    }

    // epilogue
    float*  Cf = (float*)Cv  + z * sCz;
    __half* Ch = (__half*)Cv + z * sCz;
    #pragma unroll
    for (int fm = 0; fm < 2; ++fm) {
        int r0 = bm + wm*32 + fm*16 + g;
        int r1 = r0 + 8;
        #pragma unroll
        for (int fn = 0; fn < 8; ++fn) {
            int c = bc + wn*64 + fn*8 + 2*t;
            float b0v = 0.f, b1v = 0.f;
            if (bias) { b0v = bias[c]; b1v = bias[c + 1]; }
            float v0 = acc[fm][fn][0]*alpha + b0v;
            float v1 = acc[fm][fn][1]*alpha + b1v;
            float v2 = acc[fm][fn][2]*alpha + b0v;
            float v3 = acc[fm][fn][3]*alpha + b1v;
            if (relu) {
                v0 = fmaxf(v0, 0.f); v1 = fmaxf(v1, 0.f);
                v2 = fmaxf(v2, 0.f); v3 = fmaxf(v3, 0.f);
            }
            if (outhalf) {
                if (r0 < M) *(__half2*)&Ch[(long long)r0*ldc + c] = __floats2half2_rn(v0, v1);
                if (r1 < M) *(__half2*)&Ch[(long long)r1*ldc + c] = __floats2half2_rn(v2, v3);
            } else {
                if (r0 < M) *(float2*)&Cf[(long long)r0*ldc + c] = make_float2(v0, v1);
                if (r1 < M) *(float2*)&Cf[(long long)r1*ldc + c] = make_float2(v2, v3);
            }
        }
    }
}

// ---------------- attention: fp16 flash, split-K x8, chunk=64 -----------------
#define AQS 72   // halves stride

__global__ __launch_bounds__(256, 2)
void attn_k()
{
    extern __shared__ __half smh[];
    __half* Qs = smh;                 // 128*72
    __half* Ks = Qs + 128*AQS;        // 64*72
    __half* Vs = Ks + 64*AQS;         // 64*72
    __half* Ps = Vs + 64*AQS;         // 128*72
    float* denom = (float*)(Ps + 128*AQS);   // 128
    float* rsum  = denom + 128;              // 128

    const int x = blockIdx.x;
    const int split = x & (NSPLIT - 1), bh = x >> 3;
    const int b = bh >> 3, h = bh & 7;
    const int tid = threadIdx.x, lane = tid & 31, warp = tid >> 5;
    const int g = lane >> 2, t = lane & 3;
    const int wm = warp >> 1, wn = warp & 1;

    const uint32_t qb = smem_u32(Qs), kb = smem_u32(Ks);
    const uint32_t vb = smem_u32(Vs), pb = smem_u32(Ps);

    // Q tile [128 x 64] half, zero-pad rows >= 100
    {
        int r = tid >> 1, c0 = (tid & 1) * 32;
        const float* src = g_Q + (long long)(b*SEQL + (r < SEQL ? r : 0))*DIM + h*HD + c0;
        #pragma unroll
        for (int j = 0; j < 4; ++j) {
            float4 v0 = make_float4(0.f, 0.f, 0.f, 0.f), v1 = v0;
            if (r < SEQL) { v0 = *(const float4*)(src + j*8);
                            v1 = *(const float4*)(src + j*8 + 4); }
            __half2 hq[4] = { __floats2half2_rn(v0.x, v0.y), __floats2half2_rn(v0.z, v0.w),
                              __floats2half2_rn(v1.x, v1.y), __floats2half2_rn(v1.z, v1.w) };
            *(uint4*)&Qs[r*AQS + c0 + j*8] = *(uint4*)hq;
        }
    }
    if (tid < 128) denom[tid] = 0.f;

    float oacc[2][4][4];
    #pragma unroll
    for (int i = 0; i < 2; ++i)
        #pragma unroll
        for (int j = 0; j < 4; ++j)
            #pragma unroll
            for (int k = 0; k < 4; ++k) oacc[i][j][k] = 0.f;

    const int k0 = split * SPLEN;
    #pragma unroll 1
    for (int c0k = k0; c0k < k0 + SPLEN; c0k += 64) {
        __syncthreads();   // prior chunk done with Ks/Vs/Ps and rsum consumed
        {
            int r = tid >> 2, cc = (tid & 3) * 16;
            long long off = (long long)(b*HW + c0k + r)*DIM + h*HD + cc;
            *(uint4*)&Ks[r*AQS + cc]     = *(const uint4*)&g_K2[off];
            *(uint4*)&Ks[r*AQS + cc + 8] = *(const uint4*)&g_K2[off + 8];
            *(uint4*)&Vs[r*AQS + cc]     = *(const uint4*)&g_V2[off];
            *(uint4*)&Vs[r*AQS + cc + 8] = *(const uint4*)&g_V2[off + 8];
        }
        if (tid < 128) rsum[tid] = 0.f;
        __syncthreads();

        // S = Q @ K^T  (warp: 32 q-rows x 32 keys)
        float sacc[2][4][4];
        #pragma unroll
        for (int i = 0; i < 2; ++i)
            #pragma unroll
            for (int j = 0; j < 4; ++j)
                #pragma unroll
                for (int k = 0; k < 4; ++k) sacc[i][j][k] = 0.f;
        #pragma unroll
        for (int ks = 0; ks < 4; ++ks) {
            uint32_t afr[2][4];
            #pragma unroll
            for (int fm = 0; fm < 2; ++fm)
                ldm4(afr[fm], qb + (uint32_t)((wm*32 + fm*16 + (lane & 15))*AQS
                                              + ks*16 + (lane >> 4)*8) * 2u);
            #pragma unroll
            for (int nb = 0; nb < 2; ++nb) {
                uint32_t bfr[4];
                ldm4(bfr, kb + (uint32_t)((wn*32 + nb*16 + (lane >> 4)*8 + (lane & 7))*AQS
                                          + ks*16 + ((lane >> 3) & 1)*8) * 2u);
                #pragma unroll
                for (int fm = 0; fm < 2; ++fm) {
                    mmah(sacc[fm][2*nb],     afr[fm], bfr[0], bfr[1]);
                    mmah(sacc[fm][2*nb + 1], afr[fm], bfr[2], bfr[3]);
                }
            }
        }

        // P = exp(S): pack to half into Ps, accumulate row sums
        #pragma unroll
        for (int fm = 0; fm < 2; ++fm) {
            float rs0 = 0.f, rs1 = 0.f;
            int row0 = wm*32 + fm*16 + g;
            #pragma unroll
            for (int fn = 0; fn < 4; ++fn) {
                float p0 = ex2f(sacc[fm][fn][0] * LOG2E);
                float p1 = ex2f(sacc[fm][fn][1] * LOG2E);
                float p2 = ex2f(sacc[fm][fn][2] * LOG2E);
                float p3 = ex2f(sacc[fm][fn][3] * LOG2E);
                rs0 += p0 + p1; rs1 += p2 + p3;
                int c = wn*32 + fn*8 + 2*t;
                *(__half2*)&Ps[row0*AQS + c]       = __floats2half2_rn(p0, p1);
                *(__half2*)&Ps[(row0 + 8)*AQS + c] = __floats2half2_rn(p2, p3);
            }
            rs0 += __shfl_xor_sync(0xffffffffu, rs0, 1);
            rs0 += __shfl_xor_sync(0xffffffffu, rs0, 2);
            rs1 += __shfl_xor_sync(0xffffffffu, rs1, 1);
            rs1 += __shfl_xor_sync(0xffffffffu, rs1, 2);
            if (t == 0) {
                atomicAdd(&rsum[row0], rs0);
                atomicAdd(&rsum[row0 + 8], rs1);
            }
        }
        __syncthreads();   // Ps + rsum complete
        if (tid < 128) denom[tid] += rsum[tid];

        // O += P @ V (warp: 32 rows x 32 d, over 64 keys)
        #pragma unroll
        for (int kk = 0; kk < 4; ++kk) {
            uint32_t afr[2][4];
            #pragma unroll
            for (int fm = 0; fm < 2; ++fm)
                ldm4(afr[fm], pb + (uint32_t)((wm*32 + fm*16 + (lane & 15))*AQS
                                              + kk*16 + (lane >> 4)*8) * 2u);
            #pragma unroll
            for (int nb = 0; nb < 2; ++nb) {
                uint32_t bfr[4];
                ldm4t(bfr, vb + (uint32_t)((kk*16 + ((lane >> 3) & 1)*8 + (lane & 7))*AQS
                                           + wn*32 + nb*16 + (lane >> 4)*8) * 2u);
                #pragma unroll
                for (int fm = 0; fm < 2; ++fm) {
                    mmah(oacc[fm][2*nb],     afr[fm], bfr[0], bfr[1]);
                    mmah(oacc[fm][2*nb + 1], afr[fm], bfr[2], bfr[3]);
                }
            }
        }
    }

    // write partial numerators + denominators
    #pragma unroll
    for (int fm = 0; fm < 2; ++fm) {
        int row0 = wm*32 + fm*16 + g;
        int row1 = row0 + 8;
        #pragma unroll
        for (int fn = 0; fn < 4; ++fn) {
            int c = wn*32 + fn*8 + 2*t;
            if (row0 < SEQL)
                *(float2*)&g_PO[((long long)x*SEQL + row0)*HD + c] =
                    make_float2(oacc[fm][fn][0], oacc[fm][fn][1]);
            if (row1 < SEQL)
                *(float2*)&g_PO[((long long)x*SEQL + row1)*HD + c] =
                    make_float2(oacc[fm][fn][2], oacc[fm][fn][3]);
        }
    }
    if (tid < 128) g_PD[x*128 + tid] = denom[tid];
}

// ---------------- attention reduce --------------------------------------------
__global__ void attn_reduce()
{
    const int row = blockIdx.x;            // b*100 + l
    const int b = row / SEQL, l = row % SEQL;
    const int c = threadIdx.x;             // 0..511
    const int h = c >> 6, d = c & 63;
    const int xb = (b * NHEAD + h) * NSPLIT;
    float num = 0.f, den = 0.f;
    #pragma unroll
    for (int s = 0; s < NSPLIT; ++s) {
        num += g_PO[((long long)(xb + s)*SEQL + l)*HD + d];
        den += g_PD[(xb + s)*128 + l];
    }
    g_AO[(long long)row * DIM + c] = num / den;
}

// ---------------- LayerNorm(a + t) ---------------------------------------------
__global__ void ln_add_k(const float* __restrict__ a, const float* __restrict__ tt,
                         const float* __restrict__ w, const float* __restrict__ bb,
                         float* __restrict__ o)
{
    __shared__ float red[4];
    __shared__ float smu, sinv;
    int row = blockIdx.x, tid = threadIdx.x;   // 128 threads
    const float* pa = a  + (long long)row * DIM;
    const float* pt = tt + (long long)row * DIM;
    float v[4]; float s = 0.f;
    #pragma unroll
    for (int i = 0; i < 4; ++i) {
        v[i] = pa[tid + i*128] + pt[tid + i*128];
        s += v[i];
    }
    #pragma unroll
    for (int off = 16; off; off >>= 1) s += __shfl_xor_sync(0xffffffffu, s, off);
    if ((tid & 31) == 0) red[tid >> 5] = s;
    __syncthreads();
    if (tid == 0) smu = (red[0] + red[1] + red[2] + red[3]) * (1.f / 512.f);
    __syncthreads();
    float mu = smu; float s2 = 0.f;
    #pragma unroll
    for (int i = 0; i < 4; ++i) { float d = v[i] - mu; s2 += d * d; }
    #pragma unroll
    for (int off = 16; off; off >>= 1) s2 += __shfl_xor_sync(0xffffffffu, s2, off);
    if ((tid & 31) == 0) red[tid >> 5] = s2;
    __syncthreads();
    if (tid == 0) sinv = rsqrtf((red[0] + red[1] + red[2] + red[3]) * (1.f / 512.f) + 1e-5f);
    __syncthreads();
    float inv = sinv;
    #pragma unroll
    for (int i = 0; i < 4; ++i) {
        int c = tid + i*128;
        o[(long long)row * DIM + c] = (v[i] - mu) * inv * w[c] + bb[c];
    }
}

// ---------------- launch ---------------------------------------------------------
extern "C" void kernel_launch(void* const* d_in, const int* in_sizes, int n_in,
                              void* d_out, int out_size)
{
    const float* query = (const float*)d_in[0];
    const float* feats = (const float*)d_in[1];
    const float* Wq    = (const float*)d_in[2];
    const float* Wk    = (const float*)d_in[3];
    const float* Wv    = (const float*)d_in[4];
    const float* Wp    = (const float*)d_in[5];
    const float* bp    = (const float*)d_in[6];
    const float* W1    = (const float*)d_in[7];
    const float* b1    = (const float*)d_in[8];
    const float* W2    = (const float*)d_in[9];
    const float* b2    = (const float*)d_in[10];
    const float* ln0w  = (const float*)d_in[11];
    const float* ln0b  = (const float*)d_in[12];
    const float* ln2w  = (const float*)d_in[13];
    const float* ln2b  = (const float*)d_in[14];
    float* out = (float*)d_out;

    __half *pK2, *pV2;
    float *pQ, *pAO, *pT, *pX, *pH;
    cudaGetSymbolAddress((void**)&pK2, g_K2);
    cudaGetSymbolAddress((void**)&pV2, g_V2);
    cudaGetSymbolAddress((void**)&pQ,  g_Q);
    cudaGetSymbolAddress((void**)&pAO, g_AO);
    cudaGetSymbolAddress((void**)&pT,  g_T);
    cudaGetSymbolAddress((void**)&pX,  g_X);
    cudaGetSymbolAddress((void**)&pH,  g_H);

    const int AS = (128*AQS + 64*AQS + 64*AQS + 128*AQS) * 2 + 256 * 4;  // 56320
    cudaFuncSetAttribute(attn_k, cudaFuncAttributeMaxDynamicSharedMemorySize, AS);

    // 1. q = 0.125 * query @ Wq^T   -> g_Q (f32)
    gemm_h<<<dim3(4, 13, 1), 256>>>(query, Wq, Wq, pQ, pQ,
                                    MROWS, DIM, 999, 0, 0, 0.125f, nullptr, 0,
                                    0, 0, 0);
    // 2. fused K,V projections -> g_K2, g_V2 (half)
    gemm_h<<<dim3(8, 2048, 1), 256>>>(feats, Wk, Wv, pK2, pV2,
                                      NBATCH*HW, DIM, 4, 0, 1, 1.f, nullptr, 0,
                                      0, 0, 0);
    // 3. attention partials + reduce
    attn_k<<<NBATCH * NHEAD * NSPLIT, 256, AS>>>();
    attn_reduce<<<MROWS, 512>>>();
    // 4. mask = q @ K^T per batch -> d_out tail (f32), B in half
    gemm_h<<<dim3(HW/128, 1, NBATCH), 256>>>(pQ, pK2, pK2,
                                             out + (long long)MROWS*DIM,
                                             out + (long long)MROWS*DIM,
                                             SEQL, HW, 999, 1, 0, 1.f, nullptr, 0,
                                             (long long)SEQL*DIM,
                                             (long long)HW*DIM,
                                             (long long)SEQL*HW);
    // 5. attn_out @ Wp^T + bp -> g_T
    gemm_h<<<dim3(4, 13, 1), 256>>>(pAO, Wp, Wp, pT, pT,
                                    MROWS, DIM, 999, 0, 0, 1.f, bp, 0, 0, 0, 0);
    // 6. x = LN(query + t)
    ln_add_k<<<MROWS, 128>>>(query, pT, ln0w, ln0b, pX);
    // 7. h = relu(x @ W1^T + b1)
    gemm_h<<<dim3(4, 13, 1), 256>>>(pX, W1, W1, pH, pH,
                                    MROWS, DIM, 999, 0, 0, 1.f, b1, 1, 0, 0, 0);
    // 8. f = h @ W2^T + b2
    gemm_h<<<dim3(4, 13, 1), 256>>>(pH, W2, W2, pT, pT,
                                    MROWS, DIM, 999, 0, 0, 1.f, b2, 0, 0, 0, 0);
    // 9. y = LN(x + f) -> d_out head
    ln_add_k<<<MROWS, 128>>>(pX, pT, ln2w, ln2b, out);
}

// round 6
// speedup vs baseline: 2.3496x; 1.4327x over previous
#include <cuda_runtime.h>
#include <cuda_fp16.h>
#include <stdint.h>

#define NBATCH 16
#define SEQL   100
#define DIM    512
#define HW     16384
#define NHEAD  8
#define HD     64
#define MROWS  (NBATCH*SEQL)
#define LOG2E  1.4426950408889634f
#define NSPLIT 8
#define SPLEN  (HW / NSPLIT)

// ---------------- scratch (device globals; no allocation allowed) -------------
__device__ __half g_featsh[(size_t)NBATCH*HW*DIM];   // 256 MB
__device__ __half g_K2[(size_t)NBATCH*HW*DIM];       // 256 MB
__device__ __half g_V2[(size_t)NBATCH*HW*DIM];       // 256 MB
__device__ __half g_queryh[MROWS*DIM];
__device__ __half g_Wqh[DIM*DIM];
__device__ __half g_Wkh[DIM*DIM];
__device__ __half g_Wvh[DIM*DIM];
__device__ __half g_Wph[DIM*DIM];
__device__ __half g_W1h[DIM*DIM];
__device__ __half g_W2h[DIM*DIM];
__device__ __half g_Qh [MROWS*DIM];
__device__ __half g_AOh[MROWS*DIM];
__device__ __half g_Xh [MROWS*DIM];
__device__ __half g_Hh [MROWS*DIM];
__device__ float  g_X  [MROWS*DIM];
__device__ float  g_T  [MROWS*DIM];
__device__ float  g_PO[(size_t)NBATCH*NHEAD*NSPLIT*SEQL*HD];
__device__ float  g_PD[NBATCH*NHEAD*NSPLIT*128];

// ---------------- helpers ------------------------------------------------------
__device__ __forceinline__ uint32_t smem_u32(const void* p) {
    uint32_t a;
    asm("{ .reg .u64 t; cvta.to.shared.u64 t, %1; cvt.u32.u64 %0, t; }" : "=r"(a) : "l"(p));
    return a;
}
__device__ __forceinline__ void ldm4(uint32_t* r, uint32_t addr) {
    asm volatile("ldmatrix.sync.aligned.m8n8.x4.shared.b16 {%0,%1,%2,%3}, [%4];"
                 : "=r"(r[0]), "=r"(r[1]), "=r"(r[2]), "=r"(r[3]) : "r"(addr));
}
__device__ __forceinline__ void ldm4t(uint32_t* r, uint32_t addr) {
    asm volatile("ldmatrix.sync.aligned.m8n8.x4.trans.shared.b16 {%0,%1,%2,%3}, [%4];"
                 : "=r"(r[0]), "=r"(r[1]), "=r"(r[2]), "=r"(r[3]) : "r"(addr));
}
__device__ __forceinline__ void mmah(float* c, const uint32_t* a, uint32_t b0, uint32_t b1) {
    asm volatile("mma.sync.aligned.m16n8k16.row.col.f32.f16.f16.f32 "
                 "{%0,%1,%2,%3},{%4,%5,%6,%7},{%8,%9},{%0,%1,%2,%3};"
                 : "+f"(c[0]), "+f"(c[1]), "+f"(c[2]), "+f"(c[3])
                 : "r"(a[0]), "r"(a[1]), "r"(a[2]), "r"(a[3]), "r"(b0), "r"(b1));
}
__device__ __forceinline__ float ex2f(float x) {
    float y; asm("ex2.approx.f32 %0, %1;" : "=f"(y) : "f"(x)); return y;
}
__device__ __forceinline__ void cpa16(uint32_t dst, const void* src) {
    asm volatile("cp.async.ca.shared.global [%0], [%1], 16;" :: "r"(dst), "l"(src));
}

// ---------------- f32 -> f16 conversion ----------------------------------------
__global__ void cvt_h(const float* __restrict__ src, __half* __restrict__ dst, long long n)
{
    long long stride = (long long)gridDim.x * blockDim.x * 8;
    for (long long i = ((long long)blockIdx.x * blockDim.x + threadIdx.x) * 8;
         i < n; i += stride) {
        float4 a = *(const float4*)(src + i);
        float4 b = *(const float4*)(src + i + 4);
        __half2 h[4] = { __floats2half2_rn(a.x, a.y), __floats2half2_rn(a.z, a.w),
                         __floats2half2_rn(b.x, b.y), __floats2half2_rn(b.z, b.w) };
        *(uint4*)(dst + i) = *(uint4*)h;
    }
}

// ---------------- half GEMM: C = relu?(alpha * A[M,512] @ B[N,512]^T + bias) ----
// BM=128, BN=128, BK=32, cp.async double buffer, pure fp16 inputs.
#define GS2 40   // halves stride (80 B): conflict-free ldmatrix

__global__ __launch_bounds__(256, 2)
void gemm_hh(const __half* __restrict__ A,
             const __half* __restrict__ B0, const __half* __restrict__ B1,
             void* __restrict__ C0v, void* __restrict__ C1v,
             int M, int ldc, int nsplitBlk, int outhalf,
             float alpha, const float* __restrict__ bias, int relu,
             long long sAz, long long sBz, long long sCz)
{
    __shared__ __half sA[2][128*GS2];
    __shared__ __half sB[2][128*GS2];
    const int tid = threadIdx.x, lane = tid & 31, warp = tid >> 5;
    const int wm = warp >> 1, wn = warp & 1;
    const int g = lane >> 2, t = lane & 3;
    const int bm = blockIdx.y * 128;
    const int bx = blockIdx.x;
    const long long z = blockIdx.z;

    const __half* Bp; void* Cv; int bc;
    if (bx >= nsplitBlk) { Bp = B1; Cv = C1v; bc = (bx - nsplitBlk) * 128; }
    else                 { Bp = B0; Cv = C0v; bc = bx * 128; }

    // loader mapping: 2 chunks of 16B per thread per matrix
    const int r0l = tid >> 2;                 // rows 0..63
    const int c8  = (tid & 3) * 8;            // half-offset 0/8/16/24
    int ar0 = bm + r0l;       if (ar0 > M - 1) ar0 = M - 1;
    int ar1 = bm + r0l + 64;  if (ar1 > M - 1) ar1 = M - 1;
    const __half* Ag0 = A + z * sAz + (long long)ar0 * 512 + c8;
    const __half* Ag1 = A + z * sAz + (long long)ar1 * 512 + c8;
    const __half* Bg0 = Bp + z * sBz + (long long)(bc + r0l) * 512 + c8;
    const __half* Bg1 = Bp + z * sBz + (long long)(bc + r0l + 64) * 512 + c8;
    const uint32_t sa = smem_u32(sA), sb = smem_u32(sB);
    const uint32_t da0 = sa + (uint32_t)(r0l * GS2 + c8) * 2u;
    const uint32_t da1 = sa + (uint32_t)((r0l + 64) * GS2 + c8) * 2u;
    const uint32_t db0 = sb + (uint32_t)(r0l * GS2 + c8) * 2u;
    const uint32_t db1 = sb + (uint32_t)((r0l + 64) * GS2 + c8) * 2u;
    const uint32_t bufb = 128 * GS2 * 2u;

    #define LOADKT(kt, buf) do {                                  \
        uint32_t o = (buf) * bufb;                                \
        cpa16(da0 + o, Ag0 + (kt)*32);                            \
        cpa16(da1 + o, Ag1 + (kt)*32);                            \
        cpa16(db0 + o, Bg0 + (kt)*32);                            \
        cpa16(db1 + o, Bg1 + (kt)*32);                            \
        asm volatile("cp.async.commit_group;");                   \
    } while (0)

    float acc[2][8][4];
    #pragma unroll
    for (int i = 0; i < 2; ++i)
        #pragma unroll
        for (int j = 0; j < 8; ++j)
            #pragma unroll
            for (int k = 0; k < 4; ++k) acc[i][j][k] = 0.f;

    LOADKT(0, 0);

    #pragma unroll 1
    for (int kt = 0; kt < 16; ++kt) {
        asm volatile("cp.async.wait_group 0;");
        __syncthreads();
        if (kt < 15) LOADKT(kt + 1, (kt + 1) & 1);
        const uint32_t ab = sa + (kt & 1) * bufb;
        const uint32_t bb = sb + (kt & 1) * bufb;
        #pragma unroll
        for (int kk = 0; kk < 2; ++kk) {
            uint32_t afr[2][4];
            #pragma unroll
            for (int fm = 0; fm < 2; ++fm)
                ldm4(afr[fm], ab + (uint32_t)((wm*32 + fm*16 + (lane & 15))*GS2
                                              + kk*16 + (lane >> 4)*8) * 2u);
            #pragma unroll
            for (int nb = 0; nb < 4; ++nb) {
                uint32_t bfr[4];
                ldm4(bfr, bb + (uint32_t)((wn*64 + nb*16 + (lane >> 4)*8 + (lane & 7))*GS2
                                          + kk*16 + ((lane >> 3) & 1)*8) * 2u);
                #pragma unroll
                for (int fm = 0; fm < 2; ++fm) {
                    mmah(acc[fm][2*nb],     afr[fm], bfr[0], bfr[1]);
                    mmah(acc[fm][2*nb + 1], afr[fm], bfr[2], bfr[3]);
                }
            }
        }
        __syncthreads();
    }

    float*  Cf = (float*)Cv  + z * sCz;
    __half* Ch = (__half*)Cv + z * sCz;
    #pragma unroll
    for (int fm = 0; fm < 2; ++fm) {
        int r0 = bm + wm*32 + fm*16 + g;
        int r1 = r0 + 8;
        #pragma unroll
        for (int fn = 0; fn < 8; ++fn) {
            int c = bc + wn*64 + fn*8 + 2*t;
            float b0v = 0.f, b1v = 0.f;
            if (bias) { b0v = bias[c]; b1v = bias[c + 1]; }
            float v0 = acc[fm][fn][0]*alpha + b0v;
            float v1 = acc[fm][fn][1]*alpha + b1v;
            float v2 = acc[fm][fn][2]*alpha + b0v;
            float v3 = acc[fm][fn][3]*alpha + b1v;
            if (relu) {
                v0 = fmaxf(v0, 0.f); v1 = fmaxf(v1, 0.f);
                v2 = fmaxf(v2, 0.f); v3 = fmaxf(v3, 0.f);
            }
            if (outhalf) {
                if (r0 < M) *(__half2*)&Ch[(long long)r0*ldc + c] = __floats2half2_rn(v0, v1);
                if (r1 < M) *(__half2*)&Ch[(long long)r1*ldc + c] = __floats2half2_rn(v2, v3);
            } else {
                if (r0 < M) *(float2*)&Cf[(long long)r0*ldc + c] = make_float2(v0, v1);
                if (r1 < M) *(float2*)&Cf[(long long)r1*ldc + c] = make_float2(v2, v3);
            }
        }
    }
}

// ---------------- attention: fp16 flash, split-K x8, chunk=64 ------------------
#define AQS 72

__global__ __launch_bounds__(256, 2)
void attn_k()
{
    extern __shared__ __half smh[];
    __half* Qs = smh;                 // 128*72
    __half* Ks = Qs + 128*AQS;        // 64*72
    __half* Vs = Ks + 64*AQS;         // 64*72
    __half* Ps = Vs + 64*AQS;         // 128*72
    float* denom = (float*)(Ps + 128*AQS);
    float* rsum  = denom + 128;

    const int x = blockIdx.x;
    const int split = x & (NSPLIT - 1), bh = x >> 3;
    const int b = bh >> 3, h = bh & 7;
    const int tid = threadIdx.x, lane = tid & 31, warp = tid >> 5;
    const int g = lane >> 2, t = lane & 3;
    const int wm = warp >> 1, wn = warp & 1;

    const uint32_t qb = smem_u32(Qs), kb = smem_u32(Ks);
    const uint32_t vb = smem_u32(Vs), pb = smem_u32(Ps);

    // Q tile [128 x 64] half; zero rows >= 100
    {
        int r = tid >> 1, c0 = (tid & 1) * 32;
        const __half* src = g_Qh + (long long)(b*SEQL + (r < SEQL ? r : 0))*DIM + h*HD + c0;
        uint4 z4 = make_uint4(0, 0, 0, 0);
        #pragma unroll
        for (int j = 0; j < 4; ++j) {
            uint4 v = (r < SEQL) ? ((const uint4*)src)[j] : z4;
            *(uint4*)&Qs[r*AQS + c0 + j*8] = v;
        }
    }
    if (tid < 128) denom[tid] = 0.f;

    float oacc[2][4][4];
    #pragma unroll
    for (int i = 0; i < 2; ++i)
        #pragma unroll
        for (int j = 0; j < 4; ++j)
            #pragma unroll
            for (int k = 0; k < 4; ++k) oacc[i][j][k] = 0.f;

    const int k0 = split * SPLEN;
    #pragma unroll 1
    for (int c0k = k0; c0k < k0 + SPLEN; c0k += 64) {
        __syncthreads();
        {
            int r = tid >> 2, cc = (tid & 3) * 16;
            long long off = (long long)(b*HW + c0k + r)*DIM + h*HD + cc;
            *(uint4*)&Ks[r*AQS + cc]     = *(const uint4*)&g_K2[off];
            *(uint4*)&Ks[r*AQS + cc + 8] = *(const uint4*)&g_K2[off + 8];
            *(uint4*)&Vs[r*AQS + cc]     = *(const uint4*)&g_V2[off];
            *(uint4*)&Vs[r*AQS + cc + 8] = *(const uint4*)&g_V2[off + 8];
        }
        if (tid < 128) rsum[tid] = 0.f;
        __syncthreads();

        float sacc[2][4][4];
        #pragma unroll
        for (int i = 0; i < 2; ++i)
            #pragma unroll
            for (int j = 0; j < 4; ++j)
                #pragma unroll
                for (int k = 0; k < 4; ++k) sacc[i][j][k] = 0.f;
        #pragma unroll
        for (int ks = 0; ks < 4; ++ks) {
            uint32_t afr[2][4];
            #pragma unroll
            for (int fm = 0; fm < 2; ++fm)
                ldm4(afr[fm], qb + (uint32_t)((wm*32 + fm*16 + (lane & 15))*AQS
                                              + ks*16 + (lane >> 4)*8) * 2u);
            #pragma unroll
            for (int nb = 0; nb < 2; ++nb) {
                uint32_t bfr[4];
                ldm4(bfr, kb + (uint32_t)((wn*32 + nb*16 + (lane >> 4)*8 + (lane & 7))*AQS
                                          + ks*16 + ((lane >> 3) & 1)*8) * 2u);
                #pragma unroll
                for (int fm = 0; fm < 2; ++fm) {
                    mmah(sacc[fm][2*nb],     afr[fm], bfr[0], bfr[1]);
                    mmah(sacc[fm][2*nb + 1], afr[fm], bfr[2], bfr[3]);
                }
            }
        }

        #pragma unroll
        for (int fm = 0; fm < 2; ++fm) {
            float rs0 = 0.f, rs1 = 0.f;
            int row0 = wm*32 + fm*16 + g;
            #pragma unroll
            for (int fn = 0; fn < 4; ++fn) {
                float p0 = ex2f(sacc[fm][fn][0] * LOG2E);
                float p1 = ex2f(sacc[fm][fn][1] * LOG2E);
                float p2 = ex2f(sacc[fm][fn][2] * LOG2E);
                float p3 = ex2f(sacc[fm][fn][3] * LOG2E);
                rs0 += p0 + p1; rs1 += p2 + p3;
                int c = wn*32 + fn*8 + 2*t;
                *(__half2*)&Ps[row0*AQS + c]       = __floats2half2_rn(p0, p1);
                *(__half2*)&Ps[(row0 + 8)*AQS + c] = __floats2half2_rn(p2, p3);
            }
            rs0 += __shfl_xor_sync(0xffffffffu, rs0, 1);
            rs0 += __shfl_xor_sync(0xffffffffu, rs0, 2);
            rs1 += __shfl_xor_sync(0xffffffffu, rs1, 1);
            rs1 += __shfl_xor_sync(0xffffffffu, rs1, 2);
            if (t == 0) {
                atomicAdd(&rsum[row0], rs0);
                atomicAdd(&rsum[row0 + 8], rs1);
            }
        }
        __syncthreads();
        if (tid < 128) denom[tid] += rsum[tid];

        #pragma unroll
        for (int kk = 0; kk < 4; ++kk) {
            uint32_t afr[2][4];
            #pragma unroll
            for (int fm = 0; fm < 2; ++fm)
                ldm4(afr[fm], pb + (uint32_t)((wm*32 + fm*16 + (lane & 15))*AQS
                                              + kk*16 + (lane >> 4)*8) * 2u);
            #pragma unroll
            for (int nb = 0; nb < 2; ++nb) {
                uint32_t bfr[4];
                ldm4t(bfr, vb + (uint32_t)((kk*16 + ((lane >> 3) & 1)*8 + (lane & 7))*AQS
                                           + wn*32 + nb*16 + (lane >> 4)*8) * 2u);
                #pragma unroll
                for (int fm = 0; fm < 2; ++fm) {
                    mmah(oacc[fm][2*nb],     afr[fm], bfr[0], bfr[1]);
                    mmah(oacc[fm][2*nb + 1], afr[fm], bfr[2], bfr[3]);
                }
            }
        }
    }

    #pragma unroll
    for (int fm = 0; fm < 2; ++fm) {
        int row0 = wm*32 + fm*16 + g;
        int row1 = row0 + 8;
        #pragma unroll
        for (int fn = 0; fn < 4; ++fn) {
            int c = wn*32 + fn*8 + 2*t;
            if (row0 < SEQL)
                *(float2*)&g_PO[((long long)x*SEQL + row0)*HD + c] =
                    make_float2(oacc[fm][fn][0], oacc[fm][fn][1]);
            if (row1 < SEQL)
                *(float2*)&g_PO[((long long)x*SEQL + row1)*HD + c] =
                    make_float2(oacc[fm][fn][2], oacc[fm][fn][3]);
        }
    }
    if (tid < 128) g_PD[x*128 + tid] = denom[tid];
}

// ---------------- attention reduce ----------------------------------------------
__global__ void attn_reduce()
{
    const int row = blockIdx.x;
    const int b = row / SEQL, l = row % SEQL;
    const int c = threadIdx.x;             // 0..511
    const int h = c >> 6, d = c & 63;
    const int xb = (b * NHEAD + h) * NSPLIT;
    float num = 0.f, den = 0.f;
    #pragma unroll
    for (int s = 0; s < NSPLIT; ++s) {
        num += g_PO[((long long)(xb + s)*SEQL + l)*HD + d];
        den += g_PD[(xb + s)*128 + l];
    }
    g_AOh[(long long)row * DIM + c] = __float2half_rn(num / den);
}

// ---------------- LayerNorm(a + t) -----------------------------------------------
__global__ void ln_add_k(const float* __restrict__ a, const float* __restrict__ tt,
                         const float* __restrict__ w, const float* __restrict__ bb,
                         float* __restrict__ o, __half* __restrict__ oh)
{
    __shared__ float red[4];
    __shared__ float smu, sinv;
    int row = blockIdx.x, tid = threadIdx.x;   // 128 threads
    const float* pa = a  + (long long)row * DIM;
    const float* pt = tt + (long long)row * DIM;
    float v[4]; float s = 0.f;
    #pragma unroll
    for (int i = 0; i < 4; ++i) {
        v[i] = pa[tid + i*128] + pt[tid + i*128];
        s += v[i];
    }
    #pragma unroll
    for (int off = 16; off; off >>= 1) s += __shfl_xor_sync(0xffffffffu, s, off);
    if ((tid & 31) == 0) red[tid >> 5] = s;
    __syncthreads();
    if (tid == 0) smu = (red[0] + red[1] + red[2] + red[3]) * (1.f / 512.f);
    __syncthreads();
    float mu = smu; float s2 = 0.f;
    #pragma unroll
    for (int i = 0; i < 4; ++i) { float d = v[i] - mu; s2 += d * d; }
    #pragma unroll
    for (int off = 16; off; off >>= 1) s2 += __shfl_xor_sync(0xffffffffu, s2, off);
    if ((tid & 31) == 0) red[tid >> 5] = s2;
    __syncthreads();
    if (tid == 0) sinv = rsqrtf((red[0] + red[1] + red[2] + red[3]) * (1.f / 512.f) + 1e-5f);
    __syncthreads();
    float inv = sinv;
    #pragma unroll
    for (int i = 0; i < 4; ++i) {
        int c = tid + i*128;
        float y = (v[i] - mu) * inv * w[c] + bb[c];
        if (o)  o [(long long)row * DIM + c] = y;
        if (oh) oh[(long long)row * DIM + c] = __float2half_rn(y);
    }
}

// ---------------- launch -----------------------------------------------------------
extern "C" void kernel_launch(void* const* d_in, const int* in_sizes, int n_in,
                              void* d_out, int out_size)
{
    const float* query = (const float*)d_in[0];
    const float* feats = (const float*)d_in[1];
    const float* Wq    = (const float*)d_in[2];
    const float* Wk    = (const float*)d_in[3];
    const float* Wv    = (const float*)d_in[4];
    const float* Wp    = (const float*)d_in[5];
    const float* bp    = (const float*)d_in[6];
    const float* W1    = (const float*)d_in[7];
    const float* b1    = (const float*)d_in[8];
    const float* W2    = (const float*)d_in[9];
    const float* b2    = (const float*)d_in[10];
    const float* ln0w  = (const float*)d_in[11];
    const float* ln0b  = (const float*)d_in[12];
    const float* ln2w  = (const float*)d_in[13];
    const float* ln2b  = (const float*)d_in[14];
    float* out = (float*)d_out;

    __half *pFh, *pK2, *pV2, *pQryh, *pWqh, *pWkh, *pWvh, *pWph, *pW1h, *pW2h;
    __half *pQh, *pAOh, *pXh, *pHh;
    float *pX, *pT;
    cudaGetSymbolAddress((void**)&pFh,   g_featsh);
    cudaGetSymbolAddress((void**)&pK2,   g_K2);
    cudaGetSymbolAddress((void**)&pV2,   g_V2);
    cudaGetSymbolAddress((void**)&pQryh, g_queryh);
    cudaGetSymbolAddress((void**)&pWqh,  g_Wqh);
    cudaGetSymbolAddress((void**)&pWkh,  g_Wkh);
    cudaGetSymbolAddress((void**)&pWvh,  g_Wvh);
    cudaGetSymbolAddress((void**)&pWph,  g_Wph);
    cudaGetSymbolAddress((void**)&pW1h,  g_W1h);
    cudaGetSymbolAddress((void**)&pW2h,  g_W2h);
    cudaGetSymbolAddress((void**)&pQh,   g_Qh);
    cudaGetSymbolAddress((void**)&pAOh,  g_AOh);
    cudaGetSymbolAddress((void**)&pXh,   g_Xh);
    cudaGetSymbolAddress((void**)&pHh,   g_Hh);
    cudaGetSymbolAddress((void**)&pX,    g_X);
    cudaGetSymbolAddress((void**)&pT,    g_T);

    const int AS = (128*AQS + 64*AQS + 64*AQS + 128*AQS) * 2 + 256 * 4;
    cudaFuncSetAttribute(attn_k, cudaFuncAttributeMaxDynamicSharedMemorySize, AS);

    // 0. conversions to half
    cvt_h<<<8192, 256>>>(feats, pFh, (long long)NBATCH*HW*DIM);
    cvt_h<<<400, 256>>>(query, pQryh, (long long)MROWS*DIM);
    cvt_h<<<128, 256>>>(Wq, pWqh, DIM*DIM);
    cvt_h<<<128, 256>>>(Wk, pWkh, DIM*DIM);
    cvt_h<<<128, 256>>>(Wv, pWvh, DIM*DIM);
    cvt_h<<<128, 256>>>(Wp, pWph, DIM*DIM);
    cvt_h<<<128, 256>>>(W1, pW1h, DIM*DIM);
    cvt_h<<<128, 256>>>(W2, pW2h, DIM*DIM);

    // 1. q = 0.125 * query @ Wq^T -> g_Qh (half)
    gemm_hh<<<dim3(4, 13, 1), 256>>>(pQryh, pWqh, pWqh, pQh, pQh,
                                     MROWS, DIM, 999, 1, 0.125f, nullptr, 0, 0, 0, 0);
    // 2. fused K,V projections -> g_K2, g_V2 (half)
    gemm_hh<<<dim3(8, 2048, 1), 256>>>(pFh, pWkh, pWvh, pK2, pV2,
                                       NBATCH*HW, DIM, 4, 1, 1.f, nullptr, 0, 0, 0, 0);
    // 3. attention partials + reduce -> g_AOh
    attn_k<<<NBATCH * NHEAD * NSPLIT, 256, AS>>>();
    attn_reduce<<<MROWS, 512>>>();
    // 4. mask = q @ K^T per batch -> d_out tail (f32)
    gemm_hh<<<dim3(HW/128, 1, NBATCH), 256>>>(pQh, pK2, pK2,
                                              out + (long long)MROWS*DIM,
                                              out + (long long)MROWS*DIM,
                                              SEQL, HW, 999, 0, 1.f, nullptr, 0,
                                              (long long)SEQL*DIM,
                                              (long long)HW*DIM,
                                              (long long)SEQL*HW);
    // 5. attn_out @ Wp^T + bp -> g_T (f32)
    gemm_hh<<<dim3(4, 13, 1), 256>>>(pAOh, pWph, pWph, pT, pT,
                                     MROWS, DIM, 999, 0, 1.f, bp, 0, 0, 0, 0);
    // 6. x = LN(query + t) -> g_X (f32) + g_Xh (half)
    ln_add_k<<<MROWS, 128>>>(query, pT, ln0w, ln0b, pX, pXh);
    // 7. h = relu(x @ W1^T + b1) -> g_Hh (half)
    gemm_hh<<<dim3(4, 13, 1), 256>>>(pXh, pW1h, pW1h, pHh, pHh,
                                     MROWS, DIM, 999, 1, 1.f, b1, 1, 0, 0, 0);
    // 8. f = h @ W2^T + b2 -> g_T (f32)
    gemm_hh<<<dim3(4, 13, 1), 256>>>(pHh, pW2h, pW2h, pT, pT,
                                     MROWS, DIM, 999, 0, 1.f, b2, 0, 0, 0, 0);
    // 9. y = LN(x + f) -> d_out head
    ln_add_k<<<MROWS, 128>>>(pX, pT, ln2w, ln2b, out, nullptr);
}